// round 13
// baseline (speedup 1.0000x reference)
#include <cuda_runtime.h>
#include <cuda_fp16.h>
#include <cstdint>

// ============================================================================
// drug[32768,4,512] f32, Wk/Wq/Wv[512,64] f32 -> out[32768,64] f32
// out[b] = max_n softmax_m( (X Wk)(X Wq)^T )[n,:] @ (X Wv),  X = drug[b] (4x512)
//
// R13: R12 pipeline (convert folded into kt loop, split commit groups,
// GA(s+2)/GB(s+2) prefetch) + the REQUIRED __syncthreads after each cp_wait:
// cp.async completion is per-thread; cross-thread visibility of the landed
// tiles (BP read by MMA warps, ST read by convert) needs the barrier.
// fp16 m16n8k16 single pass, 64x192 CTA tile, 2 CTAs/SM, 256 threads.
// ============================================================================

namespace {
constexpr int F        = 512;
constexpr int KT       = 64;
constexpr int NSLICES  = F / KT;      // 8
constexpr int MROWS    = 64;          // 16 batches per CTA
constexpr int THREADS  = 256;         // 8 warps: wr(2) x wc(4)
constexpr int PITCHC   = 200;

constexpr int PST      = 68;
constexpr int ST_BYTES = MROWS * PST * 4;          // 17408 (x2)
constexpr int AP_BYTES = 16 * 32 * 16;             // 8192 (x2)
constexpr int BP_BYTES = 4 * 4 * 3 * 32 * 16;      // 24576 (x2)
constexpr int OFF_ST   = 0;
constexpr int OFF_AP   = 2 * ST_BYTES;             // 34816
constexpr int OFF_BP   = OFF_AP + 2 * AP_BYTES;    // 51200
constexpr int SMEM_BYTES = OFF_BP + 2 * BP_BYTES;  // 100352 -> 2 CTAs/SM
}

__device__ __forceinline__ uint32_t smem_u32(const void* p) {
    uint32_t a;
    asm("{ .reg .u64 t; cvta.to.shared.u64 t, %1; cvt.u32.u64 %0, t; }"
        : "=r"(a) : "l"(p));
    return a;
}
__device__ __forceinline__ uint32_t pack_h2(float lo, float hi) {
    __half l = __float2half_rn(lo), h = __float2half_rn(hi);
    return (uint32_t)__half_as_ushort(l) | ((uint32_t)__half_as_ushort(h) << 16);
}
__device__ __forceinline__ void mma_f16(float* c, const uint32_t* a,
                                        uint32_t b0, uint32_t b1) {
    asm("mma.sync.aligned.m16n8k16.row.col.f32.f16.f16.f32 "
        "{%0,%1,%2,%3}, {%4,%5,%6,%7}, {%8,%9}, {%0,%1,%2,%3};"
        : "+f"(c[0]), "+f"(c[1]), "+f"(c[2]), "+f"(c[3])
        : "r"(a[0]), "r"(a[1]), "r"(a[2]), "r"(a[3]), "r"(b0), "r"(b1));
}
__device__ __forceinline__ void cp16(uint32_t smem_dst, const void* gmem_src) {
    asm volatile("cp.async.cg.shared.global [%0], [%1], 16;"
                 :: "r"(smem_dst), "l"(gmem_src) : "memory");
}
__device__ __forceinline__ void cp_commit() {
    asm volatile("cp.async.commit_group;" ::: "memory");
}
template <int N>
__device__ __forceinline__ void cp_wait() {
    asm volatile("cp.async.wait_group %0;" :: "n"(N) : "memory");
}

// ---- B: fp16, fragment order (one-time prepass, same mapping as R11) -------
__device__ __align__(16) uint32_t g_BP[NSLICES][6144];

__global__ void conv_w_kernel(const float* __restrict__ Wk,
                              const float* __restrict__ Wq,
                              const float* __restrict__ Wv) {
    int idx = blockIdx.x * 256 + threadIdx.x;   // 0..49151
    int pos  = idx & 3;
    int lane = (idx >> 2) & 31;
    int j    = (idx >> 7) % 3;
    int kt   = (idx / 384) & 3;
    int wc   = (idx / 1536) & 3;
    int s    = idx / 6144;

    int f  = j * 4 + pos;
    int ng = f >> 1;
    int h  = f & 1;
    int n  = wc * 48 + ng * 8 + (lane >> 2);
    int k  = s * KT + kt * 16 + (lane & 3) * 2 + h * 8;

    const float* W = (n < 64) ? Wk : ((n < 128) ? Wq : Wv);
    int col = n % 64;
    float lo = W[k * 64 + col];
    float hi = W[(k + 1) * 64 + col];
    g_BP[s][(((wc * 4 + kt) * 3 + j) * 32 + lane) * 4 + pos] = pack_h2(lo, hi);
}

// ---------------- main fused kernel ----------------
__global__ __launch_bounds__(THREADS, 2)
void attn_mma_kernel(const float* __restrict__ drug, float* __restrict__ out) {
    extern __shared__ __align__(128) char sm[];
    const uint32_t sb = smem_u32(sm);
    const int tid  = threadIdx.x;
    const int wid  = tid >> 5;
    const int lane = tid & 31;
    const int wr   = wid & 1;
    const int wc   = wid >> 1;
    const int R0   = wr * 32;
    const int C0   = wc * 48;
    const int row0 = blockIdx.x * MROWS;

    auto issue_A = [&](int s, int par) {
        uint32_t dst = sb + OFF_ST + par * ST_BYTES;
        const float* src = drug + (size_t)row0 * F + s * KT;
        #pragma unroll
        for (int i = 0; i < 4; i++) {
            int idx = tid + i * THREADS;
            int r   = idx >> 4;
            int c16 = idx & 15;
            cp16(dst + (uint32_t)(r * PST * 4 + c16 * 16),
                 src + (size_t)r * F + c16 * 4);
        }
    };
    auto issue_B = [&](int s, int buf) {
        uint32_t dst = sb + OFF_BP + buf * BP_BYTES;
        #pragma unroll
        for (int i = 0; i < 6; i++) {
            int idx = tid + i * THREADS;
            cp16(dst + (uint32_t)idx * 16, &g_BP[s][idx * 4]);
        }
    };
    // one chunk (item = tid + i*256) of ST[par] f32 -> AP[abuf] fp16 fragments
    auto convert_chunk = [&](int par, int abuf, int i) {
        const float* stf = reinterpret_cast<const float*>(sm + OFF_ST + par * ST_BYTES);
        char* apb = sm + OFF_AP + abuf * AP_BYTES;
        int item = tid + i * THREADS;    // 0..511
        int fg  = item >> 5;
        int ln  = item & 31;
        int kt  = fg >> 2;
        int wrq = (fg >> 1) & 1;
        int rtq = fg & 1;
        int r1  = wrq * 32 + rtq * 16 + (ln >> 2);
        int c   = kt * 16 + (ln & 3) * 2;
        const float* p0 = &stf[r1 * PST + c];
        const float* p1 = &stf[(r1 + 8) * PST + c];
        uint32_t a0 = pack_h2(p0[0], p0[1]);
        uint32_t a1 = pack_h2(p1[0], p1[1]);
        uint32_t a2 = pack_h2(p0[8], p0[9]);
        uint32_t a3 = pack_h2(p1[8], p1[9]);
        *reinterpret_cast<uint4*>(apb + (uint32_t)item * 16) =
            make_uint4(a0, a1, a2, a3);
    };

    float acc[2][6][4];
    #pragma unroll
    for (int i = 0; i < 2; i++)
        #pragma unroll
        for (int j = 0; j < 6; j++)
            #pragma unroll
            for (int q = 0; q < 4; q++)
                acc[i][j][q] = 0.f;

    // ---- prologue ----
    issue_A(0, 0); issue_B(0, 0); cp_commit();   // P0
    issue_A(1, 1); cp_commit();                  // GA(1)
    issue_B(1, 1); cp_commit();                  // GB(1)
    cp_wait<2>();                                // P0 landed
    __syncthreads();                             // ...and visible to all
    convert_chunk(0, 0, 0);
    convert_chunk(0, 0, 1);                      // AP[0] <- slice 0
    __syncthreads();

    // ---- main loop ----
    // top-of-s (after GA issue + wait): flying = {GB(s+1), GA(s+2)}
    for (int s = 0; s < NSLICES; s++) {
        const int buf  = s & 1;
        const int nbuf = buf ^ 1;

        if (s + 2 < NSLICES) {
            issue_A(s + 2, buf);     // ST[buf]: A(s) already converted, free
            cp_commit();             // GA(s+2)
            cp_wait<2>();            // all but {GB(s+1), GA(s+2)} landed
        } else if (s + 1 < NSLICES) {
            cp_wait<1>();            // all but {GB(s+1)} landed
        } else {
            cp_wait<0>();            // everything landed
        }
        __syncthreads();             // REQUIRED: make GB(s)/GA(s+1) writes
                                     // visible to ALL threads (cp.async wait
                                     // is per-thread completion only)

        const char* apb = sm + OFF_AP + buf * AP_BYTES;
        const char* bpb = sm + OFF_BP + buf * BP_BYTES;
        const bool  cvt = (s + 1 < NSLICES);

        #pragma unroll
        for (int kt = 0; kt < 4; kt++) {
            uint32_t a[2][4];
            #pragma unroll
            for (int rt = 0; rt < 2; rt++) {
                int fg = kt * 4 + wr * 2 + rt;
                uint4 v = *reinterpret_cast<const uint4*>(
                    apb + (uint32_t)(fg * 32 + lane) * 16);
                a[rt][0] = v.x; a[rt][1] = v.y; a[rt][2] = v.z; a[rt][3] = v.w;
            }
            uint32_t b[12];
            #pragma unroll
            for (int j = 0; j < 3; j++) {
                uint4 v = *reinterpret_cast<const uint4*>(
                    bpb + (uint32_t)(((wc * 4 + kt) * 3 + j) * 32 + lane) * 16);
                b[4 * j]     = v.x;
                b[4 * j + 1] = v.y;
                b[4 * j + 2] = v.z;
                b[4 * j + 3] = v.w;
            }
            #pragma unroll
            for (int ng = 0; ng < 6; ng++)
                #pragma unroll
                for (int rt = 0; rt < 2; rt++)
                    mma_f16(acc[rt][ng], a[rt], b[2 * ng], b[2 * ng + 1]);

            // hide A(s+1) conversion under the MMA stream (AP[nbuf] idle)
            if (kt < 2 && cvt) convert_chunk(nbuf, nbuf, kt);
        }

        __syncthreads();             // AP[nbuf] visible; BP[buf] readers done
        if (s + 2 < NSLICES) {
            issue_B(s + 2, buf);     // BP[buf] free now
            cp_commit();             // GB(s+2)
        }
    }
    __syncthreads();

    // ---- park C [64 x 192] fp32 in smem (aliases pipeline buffers) ----
    float* Cs = reinterpret_cast<float*>(sm);
    {
        int cr = lane >> 2;
        int cc = 2 * (lane & 3);
        #pragma unroll
        for (int rt = 0; rt < 2; rt++) {
            #pragma unroll
            for (int nt = 0; nt < 6; nt++) {
                int r = R0 + rt * 16 + cr;
                int c = C0 + nt * 8 + cc;
                *reinterpret_cast<float2*>(&Cs[r * PITCHC + c]) =
                    make_float2(acc[rt][nt][0], acc[rt][nt][1]);
                *reinterpret_cast<float2*>(&Cs[(r + 8) * PITCHC + c]) =
                    make_float2(acc[rt][nt][2], acc[rt][nt][3]);
            }
        }
    }
    __syncthreads();

    // ---- attention epilogue: 8 threads per batch (threads 0..127) ----
    if (tid < 128) {
        const int bl    = tid >> 3;
        const int g     = tid & 7;
        const int rbase = bl * 4;

        float kf[4][8], qf[4][8], vf[4][8];
        #pragma unroll
        for (int n = 0; n < 4; n++) {
            const float* p = &Cs[(rbase + n) * PITCHC + g * 8];
            *(float4*)&kf[n][0] = *(const float4*)(p);
            *(float4*)&kf[n][4] = *(const float4*)(p + 4);
            *(float4*)&qf[n][0] = *(const float4*)(p + 64);
            *(float4*)&qf[n][4] = *(const float4*)(p + 68);
            *(float4*)&vf[n][0] = *(const float4*)(p + 128);
            *(float4*)&vf[n][4] = *(const float4*)(p + 132);
        }

        float sc[4][4];
        #pragma unroll
        for (int n = 0; n < 4; n++)
            #pragma unroll
            for (int m = 0; m < 4; m++) {
                float a = 0.f;
                #pragma unroll
                for (int dd = 0; dd < 8; dd++)
                    a = fmaf(kf[n][dd], qf[m][dd], a);
                sc[n][m] = a;
            }
        #pragma unroll
        for (int off = 4; off > 0; off >>= 1)
            #pragma unroll
            for (int n = 0; n < 4; n++)
                #pragma unroll
                for (int m = 0; m < 4; m++)
                    sc[n][m] += __shfl_xor_sync(0xffffffffu, sc[n][m], off);

        float res[8];
        #pragma unroll
        for (int dd = 0; dd < 8; dd++) res[dd] = -3.402823466e38f;

        #pragma unroll
        for (int n = 0; n < 4; n++) {
            float mx = fmaxf(fmaxf(sc[n][0], sc[n][1]), fmaxf(sc[n][2], sc[n][3]));
            float p[4];
            float sum = 0.f;
            #pragma unroll
            for (int m = 0; m < 4; m++) { p[m] = expf(sc[n][m] - mx); sum += p[m]; }
            float inv = 1.f / sum;
            #pragma unroll
            for (int dd = 0; dd < 8; dd++) {
                float o = 0.f;
                #pragma unroll
                for (int m = 0; m < 4; m++)
                    o = fmaf(p[m] * inv, vf[m][dd], o);
                res[dd] = fmaxf(res[dd], o);
            }
        }

        const int b = blockIdx.x * 16 + bl;
        float* op = &out[(size_t)b * 64 + g * 8];
        *(float4*)op       = make_float4(res[0], res[1], res[2], res[3]);
        *(float4*)(op + 4) = make_float4(res[4], res[5], res[6], res[7]);
    }
}

// ---------------- launch ----------------
extern "C" void kernel_launch(void* const* d_in, const int* in_sizes, int n_in,
                              void* d_out, int out_size) {
    const float* drug = (const float*)d_in[0];
    const float* Wk   = (const float*)d_in[1];
    const float* Wq   = (const float*)d_in[2];
    const float* Wv   = (const float*)d_in[3];
    float* out        = (float*)d_out;

    conv_w_kernel<<<49152 / 256, 256>>>(Wk, Wq, Wv);

    cudaFuncSetAttribute(attn_mma_kernel,
                         cudaFuncAttributeMaxDynamicSharedMemorySize, SMEM_BYTES);
    attn_mma_kernel<<<2048, THREADS, SMEM_BYTES>>>(drug, out);
}

// round 15
// speedup vs baseline: 1.0170x; 1.0170x over previous
#include <cuda_runtime.h>
#include <cuda_fp16.h>
#include <cstdint>

// ============================================================================
// drug[32768,4,512] f32, Wk/Wq/Wv[512,64] f32 -> out[32768,64] f32
// out[b] = max_n softmax_m( (X Wk)(X Wq)^T )[n,:] @ (X Wv),  X = drug[b] (4x512)
//
// R15: R14 (B fragments via __ldg from pre-permuted gmem, no BP smem;
// A-only cp.async pipeline; convert folded into kt loop; 1 sync/slice)
// with the slice-top order FIXED: cp_wait -> __syncthreads -> issue_A(s+2).
// The barrier now orders slice s-1's ST[buf] convert READS before GA(s+2)'s
// cp.async WRITES to ST[buf] (the R14 WAR race), plus GA(s+1)/AP visibility.
// ============================================================================

namespace {
constexpr int F        = 512;
constexpr int KT       = 64;
constexpr int NSLICES  = F / KT;      // 8
constexpr int MROWS    = 64;          // 16 batches per CTA
constexpr int THREADS  = 256;         // 8 warps: wr(2) x wc(4)
constexpr int PITCHC   = 200;

constexpr int PST      = 68;
constexpr int ST_BYTES = MROWS * PST * 4;          // 17408 (x2)
constexpr int AP_BYTES = 16 * 32 * 16;             // 8192 (x2)
constexpr int OFF_ST   = 0;
constexpr int OFF_AP   = 2 * ST_BYTES;             // 34816
constexpr int PIPE_BYTES = OFF_AP + 2 * AP_BYTES;  // 51200
constexpr int C_BYTES  = MROWS * PITCHC * 4;       // 51200 (aliases pipeline)
constexpr int SMEM_BYTES = (PIPE_BYTES > C_BYTES) ? PIPE_BYTES : C_BYTES;
}

__device__ __forceinline__ uint32_t smem_u32(const void* p) {
    uint32_t a;
    asm("{ .reg .u64 t; cvta.to.shared.u64 t, %1; cvt.u32.u64 %0, t; }"
        : "=r"(a) : "l"(p));
    return a;
}
__device__ __forceinline__ uint32_t pack_h2(float lo, float hi) {
    __half l = __float2half_rn(lo), h = __float2half_rn(hi);
    return (uint32_t)__half_as_ushort(l) | ((uint32_t)__half_as_ushort(h) << 16);
}
__device__ __forceinline__ void mma_f16(float* c, const uint32_t* a,
                                        uint32_t b0, uint32_t b1) {
    asm("mma.sync.aligned.m16n8k16.row.col.f32.f16.f16.f32 "
        "{%0,%1,%2,%3}, {%4,%5,%6,%7}, {%8,%9}, {%0,%1,%2,%3};"
        : "+f"(c[0]), "+f"(c[1]), "+f"(c[2]), "+f"(c[3])
        : "r"(a[0]), "r"(a[1]), "r"(a[2]), "r"(a[3]), "r"(b0), "r"(b1));
}
__device__ __forceinline__ void cp16(uint32_t smem_dst, const void* gmem_src) {
    asm volatile("cp.async.cg.shared.global [%0], [%1], 16;"
                 :: "r"(smem_dst), "l"(gmem_src) : "memory");
}
__device__ __forceinline__ void cp_commit() {
    asm volatile("cp.async.commit_group;" ::: "memory");
}
template <int N>
__device__ __forceinline__ void cp_wait() {
    asm volatile("cp.async.wait_group %0;" :: "n"(N) : "memory");
}

// ---- B: fp16, fragment order (one-time prepass; read by MMA warps via LDG) -
// per slice: [wc=4][kt=4][j=3][lane=32][pos=4] uint32 (2 fp16 each) = 24KB
__device__ __align__(16) uint32_t g_BP[NSLICES][6144];

__global__ void conv_w_kernel(const float* __restrict__ Wk,
                              const float* __restrict__ Wq,
                              const float* __restrict__ Wv) {
    int idx = blockIdx.x * 256 + threadIdx.x;   // 0..49151
    int pos  = idx & 3;
    int lane = (idx >> 2) & 31;
    int j    = (idx >> 7) % 3;
    int kt   = (idx / 384) & 3;
    int wc   = (idx / 1536) & 3;
    int s    = idx / 6144;

    int f  = j * 4 + pos;
    int ng = f >> 1;
    int h  = f & 1;
    int n  = wc * 48 + ng * 8 + (lane >> 2);
    int k  = s * KT + kt * 16 + (lane & 3) * 2 + h * 8;

    const float* W = (n < 64) ? Wk : ((n < 128) ? Wq : Wv);
    int col = n % 64;
    float lo = W[k * 64 + col];
    float hi = W[(k + 1) * 64 + col];
    g_BP[s][(((wc * 4 + kt) * 3 + j) * 32 + lane) * 4 + pos] = pack_h2(lo, hi);
}

// ---------------- main fused kernel ----------------
__global__ __launch_bounds__(THREADS, 2)
void attn_mma_kernel(const float* __restrict__ drug, float* __restrict__ out) {
    extern __shared__ __align__(128) char sm[];
    const uint32_t sb = smem_u32(sm);
    const int tid  = threadIdx.x;
    const int wid  = tid >> 5;
    const int lane = tid & 31;
    const int wr   = wid & 1;
    const int wc   = wid >> 1;
    const int R0   = wr * 32;
    const int C0   = wc * 48;
    const int row0 = blockIdx.x * MROWS;

    auto issue_A = [&](int s, int par) {
        uint32_t dst = sb + OFF_ST + par * ST_BYTES;
        const float* src = drug + (size_t)row0 * F + s * KT;
        #pragma unroll
        for (int i = 0; i < 4; i++) {
            int idx = tid + i * THREADS;
            int r   = idx >> 4;
            int c16 = idx & 15;
            cp16(dst + (uint32_t)(r * PST * 4 + c16 * 16),
                 src + (size_t)r * F + c16 * 4);
        }
    };
    // one chunk (item = tid + i*256) of ST[par] f32 -> AP[abuf] fp16 fragments
    auto convert_chunk = [&](int par, int abuf, int i) {
        const float* stf = reinterpret_cast<const float*>(sm + OFF_ST + par * ST_BYTES);
        char* apb = sm + OFF_AP + abuf * AP_BYTES;
        int item = tid + i * THREADS;    // 0..511
        int fg  = item >> 5;
        int ln  = item & 31;
        int kt  = fg >> 2;
        int wrq = (fg >> 1) & 1;
        int rtq = fg & 1;
        int r1  = wrq * 32 + rtq * 16 + (ln >> 2);
        int c   = kt * 16 + (ln & 3) * 2;
        const float* p0 = &stf[r1 * PST + c];
        const float* p1 = &stf[(r1 + 8) * PST + c];
        uint32_t a0 = pack_h2(p0[0], p0[1]);
        uint32_t a1 = pack_h2(p1[0], p1[1]);
        uint32_t a2 = pack_h2(p0[8], p0[9]);
        uint32_t a3 = pack_h2(p1[8], p1[9]);
        *reinterpret_cast<uint4*>(apb + (uint32_t)item * 16) =
            make_uint4(a0, a1, a2, a3);
    };

    float acc[2][6][4];
    #pragma unroll
    for (int i = 0; i < 2; i++)
        #pragma unroll
        for (int j = 0; j < 6; j++)
            #pragma unroll
            for (int q = 0; q < 4; q++)
                acc[i][j][q] = 0.f;

    // ---- prologue: A-only pipeline ----
    issue_A(0, 0); cp_commit();      // GA(0)
    issue_A(1, 1); cp_commit();      // GA(1)
    cp_wait<1>();                    // GA(0) landed; GA(1) flying
    __syncthreads();
    convert_chunk(0, 0, 0);
    convert_chunk(0, 0, 1);          // AP[0] <- slice 0 (from ST[0])

    // ---- main loop: ONE __syncthreads per slice ----
    // top-of-s flying set: {GA(s+1)} (GA(s+2) not yet issued)
    for (int s = 0; s < NSLICES; s++) {
        const int buf  = s & 1;
        const int nbuf = buf ^ 1;

        cp_wait<0>();                // GA(s+1) landed (had a full slice)
        __syncthreads();             // orders: GA(s+1) visible in ST[nbuf];
                                     // AP[buf] converts (slice s-1) visible;
                                     // slice s-1's ST[buf] reads complete
        if (s + 2 < NSLICES) {
            issue_A(s + 2, buf);     // safe NOW: ST[buf] readers are done
            cp_commit();             // flying: {GA(s+2)}
        }

        const char* apb = sm + OFF_AP + buf * AP_BYTES;
        const uint32_t bbase = (uint32_t)(wc * 4) * 3 * 32;
        const uint4* Bg = reinterpret_cast<const uint4*>(g_BP[s]);
        const bool cvt = (s + 1 < NSLICES);

        #pragma unroll
        for (int kt = 0; kt < 4; kt++) {
            uint32_t a[2][4];
            #pragma unroll
            for (int rt = 0; rt < 2; rt++) {
                int fg = kt * 4 + wr * 2 + rt;
                uint4 v = *reinterpret_cast<const uint4*>(
                    apb + (uint32_t)(fg * 32 + lane) * 16);
                a[rt][0] = v.x; a[rt][1] = v.y; a[rt][2] = v.z; a[rt][3] = v.w;
            }
            uint32_t b[12];
            #pragma unroll
            for (int j = 0; j < 3; j++) {
                uint4 v = __ldg(&Bg[bbase + (uint32_t)((kt * 3 + j) * 32 + lane)]);
                b[4 * j]     = v.x;
                b[4 * j + 1] = v.y;
                b[4 * j + 2] = v.z;
                b[4 * j + 3] = v.w;
            }
            #pragma unroll
            for (int ng = 0; ng < 6; ng++)
                #pragma unroll
                for (int rt = 0; rt < 2; rt++)
                    mma_f16(acc[rt][ng], a[rt], b[2 * ng], b[2 * ng + 1]);

            // hide A(s+1) conversion under the MMA stream:
            // reads ST[nbuf] (landed GA(s+1)), writes AP[nbuf] (idle buffer)
            if (kt < 2 && cvt) convert_chunk(nbuf, nbuf, kt);
        }
        // no trailing sync: next slice's top barrier provides all ordering
    }
    __syncthreads();     // all frag reads done before C park overwrites smem

    // ---- park C [64 x 192] fp32 in smem (aliases pipeline buffers) ----
    float* Cs = reinterpret_cast<float*>(sm);
    {
        int cr = lane >> 2;
        int cc = 2 * (lane & 3);
        #pragma unroll
        for (int rt = 0; rt < 2; rt++) {
            #pragma unroll
            for (int nt = 0; nt < 6; nt++) {
                int r = R0 + rt * 16 + cr;
                int c = C0 + nt * 8 + cc;
                *reinterpret_cast<float2*>(&Cs[r * PITCHC + c]) =
                    make_float2(acc[rt][nt][0], acc[rt][nt][1]);
                *reinterpret_cast<float2*>(&Cs[(r + 8) * PITCHC + c]) =
                    make_float2(acc[rt][nt][2], acc[rt][nt][3]);
            }
        }
    }
    __syncthreads();

    // ---- attention epilogue: 8 threads per batch (threads 0..127) ----
    if (tid < 128) {
        const int bl    = tid >> 3;
        const int g     = tid & 7;
        const int rbase = bl * 4;

        float kf[4][8], qf[4][8], vf[4][8];
        #pragma unroll
        for (int n = 0; n < 4; n++) {
            const float* p = &Cs[(rbase + n) * PITCHC + g * 8];
            *(float4*)&kf[n][0] = *(const float4*)(p);
            *(float4*)&kf[n][4] = *(const float4*)(p + 4);
            *(float4*)&qf[n][0] = *(const float4*)(p + 64);
            *(float4*)&qf[n][4] = *(const float4*)(p + 68);
            *(float4*)&vf[n][0] = *(const float4*)(p + 128);
            *(float4*)&vf[n][4] = *(const float4*)(p + 132);
        }

        float sc[4][4];
        #pragma unroll
        for (int n = 0; n < 4; n++)
            #pragma unroll
            for (int m = 0; m < 4; m++) {
                float a = 0.f;
                #pragma unroll
                for (int dd = 0; dd < 8; dd++)
                    a = fmaf(kf[n][dd], qf[m][dd], a);
                sc[n][m] = a;
            }
        #pragma unroll
        for (int off = 4; off > 0; off >>= 1)
            #pragma unroll
            for (int n = 0; n < 4; n++)
                #pragma unroll
                for (int m = 0; m < 4; m++)
                    sc[n][m] += __shfl_xor_sync(0xffffffffu, sc[n][m], off);

        float res[8];
        #pragma unroll
        for (int dd = 0; dd < 8; dd++) res[dd] = -3.402823466e38f;

        #pragma unroll
        for (int n = 0; n < 4; n++) {
            float mx = fmaxf(fmaxf(sc[n][0], sc[n][1]), fmaxf(sc[n][2], sc[n][3]));
            float p[4];
            float sum = 0.f;
            #pragma unroll
            for (int m = 0; m < 4; m++) { p[m] = expf(sc[n][m] - mx); sum += p[m]; }
            float inv = 1.f / sum;
            #pragma unroll
            for (int dd = 0; dd < 8; dd++) {
                float o = 0.f;
                #pragma unroll
                for (int m = 0; m < 4; m++)
                    o = fmaf(p[m] * inv, vf[m][dd], o);
                res[dd] = fmaxf(res[dd], o);
            }
        }

        const int b = blockIdx.x * 16 + bl;
        float* op = &out[(size_t)b * 64 + g * 8];
        *(float4*)op       = make_float4(res[0], res[1], res[2], res[3]);
        *(float4*)(op + 4) = make_float4(res[4], res[5], res[6], res[7]);
    }
}

// ---------------- launch ----------------
extern "C" void kernel_launch(void* const* d_in, const int* in_sizes, int n_in,
                              void* d_out, int out_size) {
    const float* drug = (const float*)d_in[0];
    const float* Wk   = (const float*)d_in[1];
    const float* Wq   = (const float*)d_in[2];
    const float* Wv   = (const float*)d_in[3];
    float* out        = (float*)d_out;

    conv_w_kernel<<<49152 / 256, 256>>>(Wk, Wq, Wv);

    cudaFuncSetAttribute(attn_mma_kernel,
                         cudaFuncAttributeMaxDynamicSharedMemorySize, SMEM_BYTES);
    attn_mma_kernel<<<2048, THREADS, SMEM_BYTES>>>(drug, out);
}